// round 1
// baseline (speedup 1.0000x reference)
#include <cuda_runtime.h>
#include <cuda_bf16.h>
#include <math.h>

// Problem dims (fixed for this problem instance)
#define DD 384
#define NMAX 16384
#define MMAX 6272
#define NSPL 16
#define BATCHMAX 8

// ---------------- device scratch (no allocation allowed) ----------------
__device__ float g_b2[NMAX];                  // coreset squared norms
__device__ float g_a2[MMAX];                  // patch squared norms
__device__ float g_minpart[NSPL * MMAX];      // per-split min of (b2 - 2ab)
__device__ int   g_argpart[NSPL * MMAX];      // per-split argmin
__device__ float g_score[BATCHMAX];
__device__ int   g_mp[BATCHMAX];
__device__ int   g_nn[BATCHMAX];
__device__ float g_knn_v[BATCHMAX * 8 * 9];
__device__ int   g_knn_i[BATCHMAX * 8 * 9];

// ---------------- f32x2 packed helpers ----------------
typedef unsigned long long u64;
union F2 { u64 u; float2 f; };

__device__ __forceinline__ u64 pack2(float lo, float hi) {
    u64 r;
    asm("mov.b64 %0, {%1, %2};" : "=l"(r) : "f"(lo), "f"(hi));
    return r;
}
__device__ __forceinline__ u64 fma2(u64 a, u64 b, u64 c) {
    u64 d;
    asm("fma.rn.f32x2 %0, %1, %2, %3;" : "=l"(d) : "l"(a), "l"(b), "l"(c));
    return d;
}

// ---------------- K1: squared norms of coreset rows and patch rows ----------------
__global__ void k1_norms(const float* __restrict__ A, const float* __restrict__ C,
                         int M, int N)
{
    int warp = (blockIdx.x * blockDim.x + threadIdx.x) >> 5;
    int lane = threadIdx.x & 31;
    int total = M + N;
    if (warp >= total) return;
    const float* src = (warp < N) ? (C + (size_t)warp * DD)
                                  : (A + (size_t)(warp - N) * DD);
    const float4* p = (const float4*)src;
    float s = 0.f;
    for (int j = lane; j < DD / 4; j += 32) {
        float4 v = p[j];
        s += v.x * v.x + v.y * v.y + v.z * v.z + v.w * v.w;
    }
#pragma unroll
    for (int off = 16; off; off >>= 1) s += __shfl_xor_sync(0xffffffffu, s, off);
    if (lane == 0) {
        if (warp < N) g_b2[warp] = s;
        else          g_a2[warp - N] = s;
    }
}

// ---------------- K2: distance-min GEMM ----------------
// BM=128 rows (patches), BN=64 cols (coreset), BK=16. 256 threads,
// thread (ty,tx) = (tid>>4, tid&15) owns 8 rows x 4 cols, packed as f32x2 row pairs.
#define BM 128
#define BN 64
#define BK 16

__global__ void __launch_bounds__(256, 2)
k2_mindist(const float* __restrict__ A, const float* __restrict__ C,
           int M, int nchunk)
{
    __shared__ __align__(16) float As[BK][BM];
    __shared__ __align__(16) float Bs[BK][BN];

    const int tid = threadIdx.x;
    const int tx = tid & 15, ty = tid >> 4;
    const int row0 = blockIdx.x * BM;
    const int split = blockIdx.y;
    const int nbase = split * nchunk;

    float runv[8];
    int   runi[8];
#pragma unroll
    for (int i = 0; i < 8; i++) { runv[i] = 3.4e38f; runi[i] = 0; }

    for (int nt = 0; nt < nchunk; nt += BN) {
        const int ncol0 = nbase + nt;
        F2 acc[4][4];
#pragma unroll
        for (int i = 0; i < 4; i++)
#pragma unroll
            for (int j = 0; j < 4; j++) acc[i][j].u = 0ull;

        for (int k0 = 0; k0 < DD; k0 += BK) {
            // load A tile (coalesced; transpose into k-major smem)
            {
                int f = tid;
#pragma unroll
                for (int rep = 0; rep < 2; rep++, f += 256) {
                    int r = f >> 2, kg = (f & 3) << 2;
                    float4 v = *(const float4*)(A + (size_t)(row0 + r) * DD + k0 + kg);
                    As[kg + 0][r] = v.x; As[kg + 1][r] = v.y;
                    As[kg + 2][r] = v.z; As[kg + 3][r] = v.w;
                }
                int r = tid >> 2, kg = (tid & 3) << 2;
                float4 v = *(const float4*)(C + (size_t)(ncol0 + r) * DD + k0 + kg);
                Bs[kg + 0][r] = v.x; Bs[kg + 1][r] = v.y;
                Bs[kg + 2][r] = v.z; Bs[kg + 3][r] = v.w;
            }
            __syncthreads();

#pragma unroll
            for (int kk = 0; kk < BK; kk++) {
                float4 av0 = *(const float4*)&As[kk][ty * 8];
                float4 av1 = *(const float4*)&As[kk][ty * 8 + 4];
                F2 a[4];
                a[0].f = make_float2(av0.x, av0.y);
                a[1].f = make_float2(av0.z, av0.w);
                a[2].f = make_float2(av1.x, av1.y);
                a[3].f = make_float2(av1.z, av1.w);
                float4 bv = *(const float4*)&Bs[kk][tx * 4];
                u64 b0 = pack2(bv.x, bv.x);
                u64 b1 = pack2(bv.y, bv.y);
                u64 b2p = pack2(bv.z, bv.z);
                u64 b3 = pack2(bv.w, bv.w);
#pragma unroll
                for (int i = 0; i < 4; i++) {
                    acc[i][0].u = fma2(a[i].u, b0,  acc[i][0].u);
                    acc[i][1].u = fma2(a[i].u, b1,  acc[i][1].u);
                    acc[i][2].u = fma2(a[i].u, b2p, acc[i][2].u);
                    acc[i][3].u = fma2(a[i].u, b3,  acc[i][3].u);
                }
            }
            __syncthreads();
        }

        // epilogue: d = b2[n] - 2*dot ; running (min, argmin)
#pragma unroll
        for (int j = 0; j < 4; j++) {
            int n = ncol0 + tx * 4 + j;
            float bb = g_b2[n];
#pragma unroll
            for (int i = 0; i < 4; i++) {
                float d0 = fmaf(-2.f, acc[i][j].f.x, bb);
                float d1 = fmaf(-2.f, acc[i][j].f.y, bb);
                int r0 = 2 * i, r1 = 2 * i + 1;
                if (d0 < runv[r0]) { runv[r0] = d0; runi[r0] = n; }
                if (d1 < runv[r1]) { runv[r1] = d1; runi[r1] = n; }
            }
        }
    }

    // reduce across the 16 tx lanes sharing each row (lexicographic: value, then index)
#pragma unroll
    for (int i = 0; i < 8; i++) {
        float v = runv[i];
        int ix = runi[i];
#pragma unroll
        for (int off = 8; off; off >>= 1) {
            float ov = __shfl_xor_sync(0xffffffffu, v, off);
            int   oi = __shfl_xor_sync(0xffffffffu, ix, off);
            if (ov < v || (ov == v && oi < ix)) { v = ov; ix = oi; }
        }
        if (tx == 0) {
            int grow = row0 + ty * 8 + i;
            g_minpart[split * M + grow] = v;
            g_argpart[split * M + grow] = ix;
        }
    }
}

// ---------------- K3: combine splits, patch scores, per-batch argmax ----------------
__global__ void k3_scores(int M, int P)
{
    int b = blockIdx.x;
    int tid = threadIdx.x;
    float bestv = -1.f;
    int bestm = 0x7fffffff, bestnn = 0;
    for (int p = tid; p < P; p += blockDim.x) {
        int m = b * P + p;
        float v = 3.4e38f;
        int ix = 0x7fffffff;
#pragma unroll
        for (int s = 0; s < NSPL; s++) {
            float pv = g_minpart[s * M + m];
            int   pi = g_argpart[s * M + m];
            if (pv < v || (pv == v && pi < ix)) { v = pv; ix = pi; }
        }
        float sc = sqrtf(fmaxf(g_a2[m] + v, 0.f));
        if (sc > bestv || (sc == bestv && m < bestm)) { bestv = sc; bestm = m; bestnn = ix; }
    }
    __shared__ float sv[256];
    __shared__ int sm_[256];
    __shared__ int sn[256];
    sv[tid] = bestv; sm_[tid] = bestm; sn[tid] = bestnn;
    __syncthreads();
    for (int off = 128; off; off >>= 1) {
        if (tid < off) {
            if (sv[tid + off] > sv[tid] ||
                (sv[tid + off] == sv[tid] && sm_[tid + off] < sm_[tid])) {
                sv[tid] = sv[tid + off]; sm_[tid] = sm_[tid + off]; sn[tid] = sn[tid + off];
            }
        }
        __syncthreads();
    }
    if (tid == 0) { g_score[b] = sv[0]; g_mp[b] = sm_[0]; g_nn[b] = sn[0]; }
}

// ---------------- K4: per (batch, split-of-8) local 9-NN of nn_sample in coreset ----------------
__global__ void k4_knn(const float* __restrict__ C, int N)
{
    int sp = blockIdx.x;   // 0..7 (N split into 8 chunks of 2048)
    int b = blockIdx.y;
    int tid = threadIdx.x; // 256
    __shared__ __align__(16) float q[DD];
    __shared__ float dv[2048];
    __shared__ int   dn[2048];
    __shared__ float rv[256];
    __shared__ int   rn_[256];
    __shared__ int   rcc[256];

    int nn = g_nn[b];
    for (int j = tid; j < DD; j += 256) q[j] = C[(size_t)nn * DD + j];
    __syncthreads();
    float qn = g_b2[nn];
    int n0 = sp * (N / 8);
    const float4* pq = (const float4*)q;
    for (int c = tid; c < N / 8; c += 256) {
        int n = n0 + c;
        const float4* p = (const float4*)(C + (size_t)n * DD);
        float dot = 0.f;
#pragma unroll 8
        for (int j = 0; j < DD / 4; j++) {
            float4 a = p[j], bq = pq[j];
            dot += a.x * bq.x + a.y * bq.y + a.z * bq.z + a.w * bq.w;
        }
        dv[c] = fmaxf(qn + g_b2[n] - 2.f * dot, 0.f);
        dn[c] = n;
    }
    __syncthreads();

    for (int k = 0; k < 9; k++) {
        float v = 3.4e38f;
        int nix = 0x7fffffff, ci = 0;
        for (int c = tid; c < N / 8; c += 256) {
            float cv = dv[c];
            if (cv < v || (cv == v && dn[c] < nix)) { v = cv; nix = dn[c]; ci = c; }
        }
        rv[tid] = v; rn_[tid] = nix; rcc[tid] = ci;
        __syncthreads();
        for (int off = 128; off; off >>= 1) {
            if (tid < off) {
                if (rv[tid + off] < rv[tid] ||
                    (rv[tid + off] == rv[tid] && rn_[tid + off] < rn_[tid])) {
                    rv[tid] = rv[tid + off]; rn_[tid] = rn_[tid + off]; rcc[tid] = rcc[tid + off];
                }
            }
            __syncthreads();
        }
        if (tid == 0) {
            int o = (b * 8 + sp) * 9 + k;
            g_knn_v[o] = rv[0];
            g_knn_i[o] = rn_[0];
            dv[rcc[0]] = 3.4e38f;
        }
        __syncthreads();
    }
}

// ---------------- K5: merge candidates, d_sup, softmax weight ----------------
__global__ void k5_final(const float* __restrict__ A, const float* __restrict__ C,
                         float* __restrict__ out)
{
    int b = blockIdx.x;
    int lane = threadIdx.x; // 32
    float lv[3];
    int ln[3];
#pragma unroll
    for (int t = 0; t < 3; t++) {
        int i = lane + 32 * t;
        if (i < 72) { lv[t] = g_knn_v[b * 72 + i]; ln[t] = g_knn_i[b * 72 + i]; }
        else        { lv[t] = 3.4e38f; ln[t] = 0x7fffffff; }
    }
    int sup[9];
    for (int k = 0; k < 9; k++) {
        float v = 3.4e38f;
        int nix = 0x7fffffff;
#pragma unroll
        for (int t = 0; t < 3; t++)
            if (lv[t] < v || (lv[t] == v && ln[t] < nix)) { v = lv[t]; nix = ln[t]; }
#pragma unroll
        for (int off = 16; off; off >>= 1) {
            float ov = __shfl_xor_sync(0xffffffffu, v, off);
            int   oi = __shfl_xor_sync(0xffffffffu, nix, off);
            if (ov < v || (ov == v && oi < nix)) { v = ov; nix = oi; }
        }
        sup[k] = nix;
#pragma unroll
        for (int t = 0; t < 3; t++)
            if (ln[t] == nix) lv[t] = 3.4e38f;
    }

    int mp = g_mp[b];
    float a2m = g_a2[mp];
    const float4* fq = (const float4*)(A + (size_t)mp * DD);
    float dsup[9];
    for (int k = 0; k < 9; k++) {
        const float4* fc = (const float4*)(C + (size_t)sup[k] * DD);
        float dot = 0.f;
        for (int j = lane; j < DD / 4; j += 32) {
            float4 x = fq[j], y = fc[j];
            dot += x.x * y.x + x.y * y.y + x.z * y.z + x.w * y.w;
        }
#pragma unroll
        for (int off = 16; off; off >>= 1) dot += __shfl_xor_sync(0xffffffffu, dot, off);
        dsup[k] = sqrtf(fmaxf(a2m + g_b2[sup[k]] - 2.f * dot, 0.f));
    }
    float mx = dsup[0];
#pragma unroll
    for (int k = 1; k < 9; k++) mx = fmaxf(mx, dsup[k]);
    float s = 0.f;
#pragma unroll
    for (int k = 0; k < 9; k++) s += expf(dsup[k] - mx);
    float w = 1.f - expf(dsup[0] - mx) / s;
    if (lane == 0) out[b] = w * g_score[b];
}

// ---------------- launch ----------------
extern "C" void kernel_launch(void* const* d_in, const int* in_sizes, int n_in,
                              void* d_out, int out_size)
{
    const float* A = (const float*)d_in[0];  // embedding [M, 384]
    const float* C = (const float*)d_in[1];  // coreset   [N, 384]
    float* out = (float*)d_out;

    int M = in_sizes[0] / DD;   // 6272
    int N = in_sizes[1] / DD;   // 16384
    int B = out_size;           // 8
    int P = M / B;              // 784
    int nchunk = N / NSPL;      // 1024

    {   // K1: norms
        int warps = M + N;
        int blocks = (warps * 32 + 255) / 256;
        k1_norms<<<blocks, 256>>>(A, C, M, N);
    }
    {   // K2: distance-min GEMM
        dim3 grid(M / BM, NSPL);
        k2_mindist<<<grid, 256>>>(A, C, M, nchunk);
    }
    k3_scores<<<B, 256>>>(M, P);
    {
        dim3 grid(8, B);
        k4_knn<<<grid, 256>>>(C, N);
    }
    k5_final<<<B, 32>>>(A, C, out);
}

// round 7
// speedup vs baseline: 2.7644x; 2.7644x over previous
#include <cuda_runtime.h>
#include <cuda_bf16.h>
#include <math.h>
#include <stdint.h>

// ---------------- problem dims ----------------
#define DD 384
#define NMAX 16384
#define MMAX 6272
#define NSPL 3
#define BATCHMAX 8
#define K4SPL 32
#define K4CH (NMAX / K4SPL)     // 512
#define NCAND (K4SPL * 9)       // 288

// ---------------- K2 tiling ----------------
#define MT 128
#define NT 256
#define BK 32
#define NTILES (NMAX / NT)      // 64
#define CHUNKS (DD / BK)        // 12
#define ASTR 40                 // padded row stride in bf16 elements (80 bytes, 16B-aligned)
#define ROWB (ASTR * 2)         // 80 bytes per row
#define AHI 0
#define ALO (MT * ROWB)                 // 10240
#define BHI (2 * MT * ROWB)             // 20480
#define BLO (2 * MT * ROWB + NT * ROWB) // 40960
#define STAGE (2 * MT * ROWB + 2 * NT * ROWB)  // 61440
#define SM_B2 0                 // 2 x 256 floats = 2048
#define SM_RED 2048             // 2048 float + 2048 int = 4096
#define SM_STG 6144
#define SMEM_TOTAL (SM_STG + 3 * STAGE)   // 190464

// ---------------- device scratch ----------------
__device__ float g_b2[NMAX];
__device__ float g_a2[MMAX];
__device__ float g_minpart[NSPL * MMAX];
__device__ int   g_argpart[NSPL * MMAX];
__device__ float g_score[BATCHMAX];
__device__ int   g_mp[BATCHMAX];
__device__ int   g_nn[BATCHMAX];
__device__ float g_knn_v[BATCHMAX * NCAND];
__device__ int   g_knn_i[BATCHMAX * NCAND];

__device__ __nv_bfloat16 g_Ahi[(size_t)MMAX * DD];
__device__ __nv_bfloat16 g_Alo[(size_t)MMAX * DD];
__device__ __nv_bfloat16 g_Chi[(size_t)NMAX * DD];
__device__ __nv_bfloat16 g_Clo[(size_t)NMAX * DD];

// ---------------- helpers ----------------
__device__ __forceinline__ uint32_t smem_u32(const void* p) {
    uint32_t a;
    asm("{ .reg .u64 t; cvta.to.shared.u64 t, %1; cvt.u32.u64 %0, t; }" : "=r"(a) : "l"(p));
    return a;
}
__device__ __forceinline__ void cpa16(uint32_t dst, const void* src) {
    asm volatile("cp.async.cg.shared.global [%0], [%1], 16;"
                 :: "r"(dst), "l"(__cvta_generic_to_global(src)) : "memory");
}
__device__ __forceinline__ void cpa_commit() {
    asm volatile("cp.async.commit_group;" ::: "memory");
}
__device__ __forceinline__ uint32_t lds32(uint32_t a) {
    uint32_t v; asm volatile("ld.shared.b32 %0, [%1];" : "=r"(v) : "r"(a)); return v;
}
__device__ __forceinline__ void mma16816(float* c, uint32_t a0, uint32_t a1, uint32_t a2,
                                         uint32_t a3, uint32_t b0, uint32_t b1) {
    asm volatile(
        "mma.sync.aligned.m16n8k16.row.col.f32.bf16.bf16.f32 "
        "{%0,%1,%2,%3}, {%4,%5,%6,%7}, {%8,%9}, {%0,%1,%2,%3};"
        : "+f"(c[0]), "+f"(c[1]), "+f"(c[2]), "+f"(c[3])
        : "r"(a0), "r"(a1), "r"(a2), "r"(a3), "r"(b0), "r"(b1));
}

// ---------------- K0: fp32 -> (hi, lo) bf16 split ----------------
__global__ void k0_convert(const float* __restrict__ A, const float* __restrict__ C,
                           int M, int N)
{
    size_t nvA = (size_t)M * DD / 4;
    size_t nvC = (size_t)N * DD / 4;
    size_t v = (size_t)blockIdx.x * blockDim.x + threadIdx.x;
    if (v >= nvA + nvC) return;
    float4 x;
    __nv_bfloat16 *ph, *pl;
    if (v < nvA) {
        x = ((const float4*)A)[v];
        ph = g_Ahi + v * 4; pl = g_Alo + v * 4;
    } else {
        size_t w = v - nvA;
        x = ((const float4*)C)[w];
        ph = g_Chi + w * 4; pl = g_Clo + w * 4;
    }
    float xs[4] = {x.x, x.y, x.z, x.w};
#pragma unroll
    for (int i = 0; i < 4; i++) {
        __nv_bfloat16 h = __float2bfloat16(xs[i]);
        __nv_bfloat16 l = __float2bfloat16(xs[i] - __bfloat162float(h));
        ph[i] = h; pl[i] = l;
    }
}

// ---------------- K1: squared norms ----------------
__global__ void k1_norms(const float* __restrict__ A, const float* __restrict__ C,
                         int M, int N)
{
    int warp = (blockIdx.x * blockDim.x + threadIdx.x) >> 5;
    int lane = threadIdx.x & 31;
    int total = M + N;
    if (warp >= total) return;
    const float* src = (warp < N) ? (C + (size_t)warp * DD)
                                  : (A + (size_t)(warp - N) * DD);
    const float4* p = (const float4*)src;
    float s = 0.f;
    for (int j = lane; j < DD / 4; j += 32) {
        float4 v = p[j];
        s += v.x * v.x + v.y * v.y + v.z * v.z + v.w * v.w;
    }
#pragma unroll
    for (int off = 16; off; off >>= 1) s += __shfl_xor_sync(0xffffffffu, s, off);
    if (lane == 0) {
        if (warp < N) g_b2[warp] = s;
        else          g_a2[warp - N] = s;
    }
}

// ---------------- K2: mma.sync bf16x3 distance-min GEMM ----------------
__device__ __forceinline__ void issue_chunk(uint32_t sb, int kc, int tile, int c,
                                            int row0, int tid)
{
    uint32_t st = sb + SM_STG + (uint32_t)(kc % 3) * STAGE;
    int k0 = c * BK;
    int n0 = tile * NT;
#pragma unroll
    for (int rep = 0; rep < 2; rep++) {
        int i = tid + rep * 256;
        int r = i >> 2;
        uint32_t doff = (uint32_t)r * ROWB + (uint32_t)(i & 3) * 16;
        size_t goff = (size_t)(row0 + r) * DD + k0 + (i & 3) * 8;
        cpa16(st + AHI + doff, g_Ahi + goff);
        cpa16(st + ALO + doff, g_Alo + goff);
    }
#pragma unroll
    for (int rep = 0; rep < 4; rep++) {
        int i = tid + rep * 256;
        int r = i >> 2;
        uint32_t doff = (uint32_t)r * ROWB + (uint32_t)(i & 3) * 16;
        size_t goff = (size_t)(n0 + r) * DD + k0 + (i & 3) * 8;
        cpa16(st + BHI + doff, g_Chi + goff);
        cpa16(st + BLO + doff, g_Clo + goff);
    }
    if (c == 0 && tid < 64) {
        cpa16(sb + SM_B2 + (uint32_t)(tile & 1) * 1024 + (uint32_t)tid * 16,
              g_b2 + n0 + tid * 4);
    }
}

__global__ void __launch_bounds__(256, 1)
k2_mm(int M)
{
    extern __shared__ char smem[];
    const uint32_t sb = smem_u32(smem);
    const int tid = threadIdx.x;
    const int wid = tid >> 5, lane = tid & 31;
    const int g = lane >> 2, tg = lane & 3;
    const int wm = wid >> 2, wn = wid & 3;
    const int row0 = blockIdx.x * MT;
    const int split = blockIdx.y;
    const int t0 = (split * NTILES) / NSPL;
    const int t1 = ((split + 1) * NTILES) / NSPL;
    const int total = (t1 - t0) * CHUNKS;

    float runv[8];
    int   runi[8];
#pragma unroll
    for (int s = 0; s < 8; s++) { runv[s] = 3.4e38f; runi[s] = 0x7fffffff; }

    float acc[4][8][4];

    // prologue: 2 chunks in flight
    issue_chunk(sb, 0, t0, 0, row0, tid);
    cpa_commit();
    issue_chunk(sb, 1, t0, 1, row0, tid);
    cpa_commit();

    for (int kc = 0; kc < total; kc++) {
        const int tile = t0 + kc / CHUNKS;
        const int c = kc % CHUNKS;

        if (kc + 2 < total) {
            int k2i = kc + 2;
            issue_chunk(sb, k2i, t0 + k2i / CHUNKS, k2i % CHUNKS, row0, tid);
            cpa_commit();
        }
        if (kc + 2 < total)       asm volatile("cp.async.wait_group 2;" ::: "memory");
        else if (kc + 1 < total)  asm volatile("cp.async.wait_group 1;" ::: "memory");
        else                      asm volatile("cp.async.wait_group 0;" ::: "memory");
        __syncthreads();

        if (c == 0) {
#pragma unroll
            for (int mt = 0; mt < 4; mt++)
#pragma unroll
                for (int nt = 0; nt < 8; nt++)
#pragma unroll
                    for (int q = 0; q < 4; q++) acc[mt][nt][q] = 0.f;
        }

        const uint32_t st = sb + SM_STG + (uint32_t)(kc % 3) * STAGE;
#pragma unroll
        for (int kk = 0; kk < 2; kk++) {
            const uint32_t kb = (uint32_t)kk * 32 + (uint32_t)tg * 4;
            uint32_t ah[4][4], al[4][4];
#pragma unroll
            for (int mt = 0; mt < 4; mt++) {
                uint32_t base = st + (uint32_t)((wm * 64 + mt * 16 + g) * ROWB) + kb;
                ah[mt][0] = lds32(base + AHI);
                ah[mt][1] = lds32(base + AHI + 8 * ROWB);
                ah[mt][2] = lds32(base + AHI + 16);
                ah[mt][3] = lds32(base + AHI + 8 * ROWB + 16);
                al[mt][0] = lds32(base + ALO);
                al[mt][1] = lds32(base + ALO + 8 * ROWB);
                al[mt][2] = lds32(base + ALO + 16);
                al[mt][3] = lds32(base + ALO + 8 * ROWB + 16);
            }
#pragma unroll
            for (int nt = 0; nt < 8; nt++) {
                uint32_t nb = st + (uint32_t)((wn * 64 + nt * 8 + g) * ROWB) + kb;
                uint32_t bh0 = lds32(nb + BHI);
                uint32_t bh1 = lds32(nb + BHI + 16);
                uint32_t bl0 = lds32(nb + BLO);
                uint32_t bl1 = lds32(nb + BLO + 16);
#pragma unroll
                for (int mt = 0; mt < 4; mt++) {
                    mma16816(acc[mt][nt], ah[mt][0], ah[mt][1], ah[mt][2], ah[mt][3], bh0, bh1);
                    mma16816(acc[mt][nt], ah[mt][0], ah[mt][1], ah[mt][2], ah[mt][3], bl0, bl1);
                    mma16816(acc[mt][nt], al[mt][0], al[mt][1], al[mt][2], al[mt][3], bh0, bh1);
                }
            }
        }

        if (c == CHUNKS - 1) {
            // epilogue for this n-tile
            const float* b2s = (const float*)(smem + SM_B2) + (tile & 1) * 256;
            const int n0 = tile * NT;
#pragma unroll
            for (int mt = 0; mt < 4; mt++) {
#pragma unroll
                for (int nt = 0; nt < 8; nt++) {
                    const float* cc = acc[mt][nt];
                    int nl = wn * 64 + nt * 8 + tg * 2;
                    float b20 = b2s[nl], b21 = b2s[nl + 1];
                    float d00 = fmaf(-2.f, cc[0], b20);
                    float d01 = fmaf(-2.f, cc[1], b21);
                    float d10 = fmaf(-2.f, cc[2], b20);
                    float d11 = fmaf(-2.f, cc[3], b21);
                    int ng0 = n0 + nl, ng1 = ng0 + 1;
                    int s0 = mt * 2, s1 = mt * 2 + 1;
                    if (d00 < runv[s0]) { runv[s0] = d00; runi[s0] = ng0; }
                    if (d01 < runv[s0]) { runv[s0] = d01; runi[s0] = ng1; }
                    if (d10 < runv[s1]) { runv[s1] = d10; runi[s1] = ng0; }
                    if (d11 < runv[s1]) { runv[s1] = d11; runi[s1] = ng1; }
                }
            }
        }
        __syncthreads();
    }

    // cross-lane reduce (lanes sharing a row differ only in tg = lane&3)
    float* minv_s = (float*)(smem + SM_RED);
    int*   mini_s = (int*)(smem + SM_RED + 2048);
#pragma unroll
    for (int s = 0; s < 8; s++) {
        float v = runv[s];
        int ix = runi[s];
#pragma unroll
        for (int off = 1; off <= 2; off <<= 1) {
            float ov = __shfl_xor_sync(0xffffffffu, v, off);
            int   oi = __shfl_xor_sync(0xffffffffu, ix, off);
            if (ov < v || (ov == v && oi < ix)) { v = ov; ix = oi; }
        }
        if (tg == 0) {
            int rloc = (s >> 1) * 16 + (s & 1) * 8 + g;
            minv_s[wid * 64 + rloc] = v;
            mini_s[wid * 64 + rloc] = ix;
        }
    }
    __syncthreads();
    if (tid < 128) {
        int row = tid;
        int wmr = row >> 6, rl = row & 63;
        float v = 3.4e38f;
        int ix = 0x7fffffff;
#pragma unroll
        for (int j = 0; j < 4; j++) {
            float ov = minv_s[(wmr * 4 + j) * 64 + rl];
            int   oi = mini_s[(wmr * 4 + j) * 64 + rl];
            if (ov < v || (ov == v && oi < ix)) { v = ov; ix = oi; }
        }
        g_minpart[split * M + row0 + row] = v;
        g_argpart[split * M + row0 + row] = ix;
    }
}

// ---------------- K3: combine splits, patch scores, per-batch argmax ----------------
__global__ void k3_scores(int M, int P)
{
    int b = blockIdx.x;
    int tid = threadIdx.x;
    float bestv = -1.f;
    int bestm = 0x7fffffff, bestnn = 0;
    for (int p = tid; p < P; p += blockDim.x) {
        int m = b * P + p;
        float v = 3.4e38f;
        int ix = 0x7fffffff;
#pragma unroll
        for (int s = 0; s < NSPL; s++) {
            float pv = g_minpart[s * M + m];
            int   pi = g_argpart[s * M + m];
            if (pv < v || (pv == v && pi < ix)) { v = pv; ix = pi; }
        }
        float sc = sqrtf(fmaxf(g_a2[m] + v, 0.f));
        if (sc > bestv || (sc == bestv && m < bestm)) { bestv = sc; bestm = m; bestnn = ix; }
    }
    __shared__ float sv[256];
    __shared__ int sm_[256];
    __shared__ int sn[256];
    sv[tid] = bestv; sm_[tid] = bestm; sn[tid] = bestnn;
    __syncthreads();
    for (int off = 128; off; off >>= 1) {
        if (tid < off) {
            if (sv[tid + off] > sv[tid] ||
                (sv[tid + off] == sv[tid] && sm_[tid + off] < sm_[tid])) {
                sv[tid] = sv[tid + off]; sm_[tid] = sm_[tid + off]; sn[tid] = sn[tid + off];
            }
        }
        __syncthreads();
    }
    if (tid == 0) { g_score[b] = sv[0]; g_mp[b] = sm_[0]; g_nn[b] = sn[0]; }
}

// ---------------- K4: per (batch, split-of-32) local 9-NN ----------------
__global__ void k4_knn(const float* __restrict__ C, int N)
{
    int sp = blockIdx.x;   // 0..31
    int b = blockIdx.y;
    int tid = threadIdx.x; // 256
    __shared__ __align__(16) float q[DD];
    __shared__ float dv[K4CH];
    __shared__ float rv[256];
    __shared__ int   rc[256];

    int nn = g_nn[b];
    for (int j = tid; j < DD; j += 256) q[j] = C[(size_t)nn * DD + j];
    __syncthreads();
    float qn = g_b2[nn];
    int n0 = sp * K4CH;
    const float4* pq = (const float4*)q;
    for (int c = tid; c < K4CH; c += 256) {
        int n = n0 + c;
        const float4* p = (const float4*)(C + (size_t)n * DD);
        float dot = 0.f;
#pragma unroll 8
        for (int j = 0; j < DD / 4; j++) {
            float4 a = p[j], bq = pq[j];
            dot += a.x * bq.x + a.y * bq.y + a.z * bq.z + a.w * bq.w;
        }
        dv[c] = fmaxf(qn + g_b2[n] - 2.f * dot, 0.f);
    }
    __syncthreads();

    for (int k = 0; k < 9; k++) {
        float v = 3.4e38f;
        int ci = 0x7fffffff;
        for (int c = tid; c < K4CH; c += 256) {
            float cv = dv[c];
            if (cv < v || (cv == v && c < ci)) { v = cv; ci = c; }
        }
        rv[tid] = v; rc[tid] = ci;
        __syncthreads();
        for (int off = 128; off; off >>= 1) {
            if (tid < off) {
                if (rv[tid + off] < rv[tid] ||
                    (rv[tid + off] == rv[tid] && rc[tid + off] < rc[tid])) {
                    rv[tid] = rv[tid + off]; rc[tid] = rc[tid + off];
                }
            }
            __syncthreads();
        }
        if (tid == 0) {
            int o = (b * K4SPL + sp) * 9 + k;
            g_knn_v[o] = rv[0];
            g_knn_i[o] = n0 + rc[0];
            dv[rc[0]] = 3.4e38f;
        }
        __syncthreads();
    }
}

// ---------------- K5: merge candidates, d_sup, softmax weight ----------------
__global__ void k5_final(const float* __restrict__ A, const float* __restrict__ C,
                         float* __restrict__ out)
{
    int b = blockIdx.x;
    int lane = threadIdx.x; // 32
    float lv[9];
    int ln[9];
#pragma unroll
    for (int t = 0; t < 9; t++) {
        int i = lane + 32 * t;
        lv[t] = g_knn_v[b * NCAND + i];
        ln[t] = g_knn_i[b * NCAND + i];
    }
    int sup[9];
    for (int k = 0; k < 9; k++) {
        float v = 3.4e38f;
        int nix = 0x7fffffff;
#pragma unroll
        for (int t = 0; t < 9; t++)
            if (lv[t] < v || (lv[t] == v && ln[t] < nix)) { v = lv[t]; nix = ln[t]; }
#pragma unroll
        for (int off = 16; off; off >>= 1) {
            float ov = __shfl_xor_sync(0xffffffffu, v, off);
            int   oi = __shfl_xor_sync(0xffffffffu, nix, off);
            if (ov < v || (ov == v && oi < nix)) { v = ov; nix = oi; }
        }
        sup[k] = nix;
#pragma unroll
        for (int t = 0; t < 9; t++)
            if (ln[t] == nix) lv[t] = 3.4e38f;
    }

    int mp = g_mp[b];
    float a2m = g_a2[mp];
    const float4* fq = (const float4*)(A + (size_t)mp * DD);
    float dsup[9];
    for (int k = 0; k < 9; k++) {
        const float4* fc = (const float4*)(C + (size_t)sup[k] * DD);
        float dot = 0.f;
        for (int j = lane; j < DD / 4; j += 32) {
            float4 x = fq[j], y = fc[j];
            dot += x.x * y.x + x.y * y.y + x.z * y.z + x.w * y.w;
        }
#pragma unroll
        for (int off = 16; off; off >>= 1) dot += __shfl_xor_sync(0xffffffffu, dot, off);
        dsup[k] = sqrtf(fmaxf(a2m + g_b2[sup[k]] - 2.f * dot, 0.f));
    }
    float mx = dsup[0];
#pragma unroll
    for (int k = 1; k < 9; k++) mx = fmaxf(mx, dsup[k]);
    float s = 0.f;
#pragma unroll
    for (int k = 0; k < 9; k++) s += expf(dsup[k] - mx);
    float w = 1.f - expf(dsup[0] - mx) / s;
    if (lane == 0) out[b] = w * g_score[b];
}

// ---------------- launch ----------------
extern "C" void kernel_launch(void* const* d_in, const int* in_sizes, int n_in,
                              void* d_out, int out_size)
{
    const float* A = (const float*)d_in[0];  // embedding [M, 384]
    const float* C = (const float*)d_in[1];  // coreset   [N, 384]
    float* out = (float*)d_out;

    int M = in_sizes[0] / DD;   // 6272
    int N = in_sizes[1] / DD;   // 16384
    int B = out_size;           // 8
    int P = M / B;              // 784

    {   // K0: bf16 hi/lo split
        size_t vecs = (size_t)(M + N) * DD / 4;
        int blocks = (int)((vecs + 255) / 256);
        k0_convert<<<blocks, 256>>>(A, C, M, N);
    }
    {   // K1: norms
        int warps = M + N;
        int blocks = (warps * 32 + 255) / 256;
        k1_norms<<<blocks, 256>>>(A, C, M, N);
    }
    {   // K2: mma.sync bf16x3 distance-min GEMM
        cudaFuncSetAttribute(k2_mm, cudaFuncAttributeMaxDynamicSharedMemorySize, SMEM_TOTAL);
        dim3 grid(M / MT, NSPL);
        k2_mm<<<grid, 256, SMEM_TOTAL>>>(M);
    }
    k3_scores<<<B, 256>>>(M, P);
    {
        dim3 grid(K4SPL, B);
        k4_knn<<<grid, 256>>>(C, N);
    }
    k5_final<<<B, 32>>>(A, C, out);
}

// round 9
// speedup vs baseline: 3.6732x; 1.3288x over previous
#include <cuda_runtime.h>
#include <cuda_bf16.h>
#include <math.h>
#include <stdint.h>
#include <string.h>

// ---------------- problem dims ----------------
#define DD 384
#define NMAX 16384
#define MMAX 6272
#define NSPL 3
#define BATCHMAX 8
#define K4SPL 32
#define K4CH (NMAX / K4SPL)     // 512
#define NCAND (K4SPL * 9)       // 288

// ---------------- K2 tiling ----------------
#define MT 128
#define NT 256
#define BK 32
#define NTILES (NMAX / NT)      // 64
#define CHUNKS (DD / BK)        // 12
#define A_BYTES (MT * 128)      // 16384
#define B_BYTES (NT * 128)      // 32768
#define STAGE (A_BYTES + B_BYTES)   // 49152
#define SM_STG 6144
#define SMEM_TOTAL (SM_STG + 3 * STAGE)   // 153600

// ---------------- device scratch ----------------
__device__ float g_b2[NMAX];
__device__ float g_a2[MMAX];
__device__ float g_minpart[NSPL * MMAX];
__device__ int   g_argpart[NSPL * MMAX];
__device__ float g_score[BATCHMAX];
__device__ int   g_mp[BATCHMAX];
__device__ int   g_nn[BATCHMAX];
__device__ float g_knn_v[BATCHMAX * NCAND];
__device__ int   g_knn_i[BATCHMAX * NCAND];

// chunk-planar, hi|lo interleaved, SW128-preswizzled staging
// layout: [chunk][row][128B]; row = 32 bf16 hi (64B) | 32 bf16 lo (64B)
__device__ unsigned char g_Sa[(size_t)CHUNKS * MMAX * 128];
__device__ unsigned char g_Sc[(size_t)CHUNKS * NMAX * 128];

// ---------------- helpers ----------------
__device__ __forceinline__ uint32_t smem_u32(const void* p) {
    uint32_t a;
    asm("{ .reg .u64 t; cvta.to.shared.u64 t, %1; cvt.u32.u64 %0, t; }" : "=r"(a) : "l"(p));
    return a;
}
__device__ __forceinline__ void mbar_init(uint32_t a, uint32_t cnt) {
    asm volatile("mbarrier.init.shared.b64 [%0], %1;" :: "r"(a), "r"(cnt) : "memory");
}
__device__ __forceinline__ void mbar_expect_tx(uint32_t a, uint32_t bytes) {
    asm volatile("mbarrier.arrive.expect_tx.shared.b64 _, [%0], %1;"
                 :: "r"(a), "r"(bytes) : "memory");
}
__device__ __forceinline__ void mbar_wait(uint32_t a, uint32_t parity) {
    asm volatile(
        "{\n\t.reg .pred P1;\n\t"
        "W_%=:\n\t"
        "mbarrier.try_wait.parity.acquire.cta.shared::cta.b64 P1, [%0], %1, 0x989680;\n\t"
        "@P1 bra.uni WD_%=;\n\t"
        "bra.uni W_%=;\n\t"
        "WD_%=:\n\t}"
        :: "r"(a), "r"(parity) : "memory");
}
__device__ __forceinline__ void bulk_g2s(uint32_t dst, const void* src, uint32_t bytes,
                                         uint32_t mbar) {
    asm volatile(
        "cp.async.bulk.shared::cta.global.mbarrier::complete_tx::bytes [%0], [%1], %2, [%3];"
        :: "r"(dst), "l"(__cvta_generic_to_global(src)), "r"(bytes), "r"(mbar) : "memory");
}
__device__ __forceinline__ void ldsm4(uint32_t* r, uint32_t a) {
    asm volatile("ldmatrix.sync.aligned.m8n8.x4.shared.b16 {%0,%1,%2,%3}, [%4];"
                 : "=r"(r[0]), "=r"(r[1]), "=r"(r[2]), "=r"(r[3]) : "r"(a));
}
__device__ __forceinline__ void ldsm2(uint32_t* r, uint32_t a) {
    asm volatile("ldmatrix.sync.aligned.m8n8.x2.shared.b16 {%0,%1}, [%2];"
                 : "=r"(r[0]), "=r"(r[1]) : "r"(a));
}
__device__ __forceinline__ void mma16816(float* c, const uint32_t* a, uint32_t b0, uint32_t b1) {
    asm volatile(
        "mma.sync.aligned.m16n8k16.row.col.f32.bf16.bf16.f32 "
        "{%0,%1,%2,%3}, {%4,%5,%6,%7}, {%8,%9}, {%0,%1,%2,%3};"
        : "+f"(c[0]), "+f"(c[1]), "+f"(c[2]), "+f"(c[3])
        : "r"(a[0]), "r"(a[1]), "r"(a[2]), "r"(a[3]), "r"(b0), "r"(b1));
}

// ---------------- K0: fp32 -> staged (hi|lo, chunk-planar, pre-swizzled) ----------------
__global__ void k0_stage(const float* __restrict__ A, const float* __restrict__ C,
                         int M, int N)
{
    int totA = M * 96;
    int totC = N * 96;
    int idx = blockIdx.x * blockDim.x + threadIdx.x;
    if (idx >= totA + totC) return;
    const float* src;
    unsigned char* dstbase;
    int r, w, rows;
    if (idx < totA) {
        r = idx / 96; w = idx % 96;
        src = A + (size_t)r * DD + w * 4;
        dstbase = g_Sa; rows = M;
    } else {
        int i2 = idx - totA;
        r = i2 / 96; w = i2 % 96;
        src = C + (size_t)r * DD + w * 4;
        dstbase = g_Sc; rows = N;
    }
    float4 x = *(const float4*)src;
    float xs[4] = {x.x, x.y, x.z, x.w};
    unsigned short hs[4], ls[4];
#pragma unroll
    for (int i = 0; i < 4; i++) {
        __nv_bfloat16 h = __float2bfloat16(xs[i]);
        __nv_bfloat16 l = __float2bfloat16(xs[i] - __bfloat162float(h));
        memcpy(&hs[i], &h, 2);
        memcpy(&ls[i], &l, 2);
    }
    uint2 ph, pl;
    ph.x = (uint32_t)hs[0] | ((uint32_t)hs[1] << 16);
    ph.y = (uint32_t)hs[2] | ((uint32_t)hs[3] << 16);
    pl.x = (uint32_t)ls[0] | ((uint32_t)ls[1] << 16);
    pl.y = (uint32_t)ls[2] | ((uint32_t)ls[3] << 16);

    int c = w >> 3, j = w & 7;          // chunk, 8B-group within chunk row
    int r7 = r & 7;
    size_t base = ((size_t)c * rows + (size_t)(r & ~7)) * 128;
    uint32_t offh = (uint32_t)r7 * 128 + ((uint32_t)((j >> 1) ^ r7) << 4) + (uint32_t)(j & 1) * 8;
    uint32_t offl = (uint32_t)r7 * 128 + ((uint32_t)(((j >> 1) + 4) ^ r7) << 4) + (uint32_t)(j & 1) * 8;
    *(uint2*)(dstbase + base + offh) = ph;
    *(uint2*)(dstbase + base + offl) = pl;
}

// ---------------- K1: squared norms ----------------
__global__ void k1_norms(const float* __restrict__ A, const float* __restrict__ C,
                         int M, int N)
{
    int warp = (blockIdx.x * blockDim.x + threadIdx.x) >> 5;
    int lane = threadIdx.x & 31;
    int total = M + N;
    if (warp >= total) return;
    const float* src = (warp < N) ? (C + (size_t)warp * DD)
                                  : (A + (size_t)(warp - N) * DD);
    const float4* p = (const float4*)src;
    float s = 0.f;
    for (int j = lane; j < DD / 4; j += 32) {
        float4 v = p[j];
        s += v.x * v.x + v.y * v.y + v.z * v.z + v.w * v.w;
    }
#pragma unroll
    for (int off = 16; off; off >>= 1) s += __shfl_xor_sync(0xffffffffu, s, off);
    if (lane == 0) {
        if (warp < N) g_b2[warp] = s;
        else          g_a2[warp - N] = s;
    }
}

// ---------------- K2: bulk-DMA + ldmatrix + mma bf16x3 distance-min GEMM ----------------
__device__ __forceinline__ void issue_chunk(uint32_t sb, int kc, int t0, int row0, int M)
{
    int s = kc % 3;
    int tile = t0 + kc / CHUNKS;
    int c = kc % CHUNKS;
    uint32_t mb = sb + (uint32_t)s * 8;
    uint32_t dst = sb + SM_STG + (uint32_t)s * STAGE;
    const unsigned char* asrc = g_Sa + ((size_t)c * M + row0) * 128;
    const unsigned char* bsrc = g_Sc + ((size_t)c * NMAX + (size_t)tile * NT) * 128;
    mbar_expect_tx(mb, STAGE);
    bulk_g2s(dst, asrc, A_BYTES, mb);
    bulk_g2s(dst + A_BYTES, bsrc, B_BYTES, mb);
}

__global__ void __launch_bounds__(256, 1)
k2_mm(int M)
{
    extern __shared__ char smem[];
    const uint32_t sb = smem_u32(smem);
    const int tid = threadIdx.x;
    const int wid = tid >> 5, lane = tid & 31;
    const int tg = lane & 3;
    const int wm = wid >> 2, wn = wid & 3;
    const int row0 = blockIdx.x * MT;
    const int split = blockIdx.y;
    const int t0 = (split * NTILES) / NSPL;
    const int t1 = ((split + 1) * NTILES) / NSPL;
    const int total = (t1 - t0) * CHUNKS;

    // ldmatrix per-lane address components
    const uint32_t r15 = lane & 15;          // A: matrix row within 16
    const uint32_t r7a = r15 & 7;
    const uint32_t parta = (lane >> 4) & 1;  // A: k8-half select
    const uint32_t rb8 = lane & 7;           // B: row within 8
    const uint32_t pb = (lane >> 3) & 1;     // B: k8-half select (lanes 0-15 used)

    if (tid == 0) {
        mbar_init(sb + 0, 1);
        mbar_init(sb + 8, 1);
        mbar_init(sb + 16, 1);
    }
    __syncthreads();

    float runv[8];
    int   runi[8];
#pragma unroll
    for (int s = 0; s < 8; s++) { runv[s] = 3.4e38f; runi[s] = 0x7fffffff; }

    float acc[4][8][4];

    if (tid == 0) {
        issue_chunk(sb, 0, t0, row0, M);
        issue_chunk(sb, 1, t0, row0, M);
    }

    for (int kc = 0; kc < total; kc++) {
        const int s = kc % 3;
        const int tile = t0 + kc / CHUNKS;
        const int c = kc % CHUNKS;

        if (tid == 0 && kc + 2 < total) issue_chunk(sb, kc + 2, t0, row0, M);

        mbar_wait(sb + (uint32_t)s * 8, (kc / 3) & 1);

        if (c == 0) {
#pragma unroll
            for (int mt = 0; mt < 4; mt++)
#pragma unroll
                for (int nt = 0; nt < 8; nt++)
#pragma unroll
                    for (int q = 0; q < 4; q++) acc[mt][nt][q] = 0.f;
        }

        const uint32_t stg = sb + SM_STG + (uint32_t)s * STAGE;
        const uint32_t stgB = stg + A_BYTES;
#pragma unroll
        for (int kk = 0; kk < 2; kk++) {
            uint32_t ah[4][4], al[4][4];
            const uint32_t ggh = ((uint32_t)(kk * 2) + parta) ^ r7a;
            const uint32_t ggl = ((uint32_t)(kk * 2) + parta + 4) ^ r7a;
#pragma unroll
            for (int mt = 0; mt < 4; mt++) {
                uint32_t arow = stg + (uint32_t)((wm * 64 + mt * 16) + r15) * 128;
                ldsm4(ah[mt], arow + (ggh << 4));
                ldsm4(al[mt], arow + (ggl << 4));
            }
            const uint32_t gbh = ((uint32_t)(kk * 2) + pb) ^ rb8;
            const uint32_t gbl = ((uint32_t)(kk * 2) + pb + 4) ^ rb8;
#pragma unroll
            for (int nt = 0; nt < 8; nt++) {
                uint32_t brow = stgB + (uint32_t)((wn * 64 + nt * 8) + rb8) * 128;
                uint32_t bh[2], bl[2];
                ldsm2(bh, brow + (gbh << 4));
                ldsm2(bl, brow + (gbl << 4));
#pragma unroll
                for (int mt = 0; mt < 4; mt++) {
                    mma16816(acc[mt][nt], ah[mt], bh[0], bh[1]);
                    mma16816(acc[mt][nt], al[mt], bh[0], bh[1]);
                    mma16816(acc[mt][nt], ah[mt], bl[0], bl[1]);
                }
            }
        }

        if (c == CHUNKS - 1) {
            const int n0 = tile * NT;
#pragma unroll
            for (int nt = 0; nt < 8; nt++) {
                int nl = wn * 64 + nt * 8 + tg * 2;
                float b20 = __ldg(&g_b2[n0 + nl]);
                float b21 = __ldg(&g_b2[n0 + nl + 1]);
                int ng0 = n0 + nl, ng1 = ng0 + 1;
#pragma unroll
                for (int mt = 0; mt < 4; mt++) {
                    const float* cc = acc[mt][nt];
                    float d00 = fmaf(-2.f, cc[0], b20);
                    float d01 = fmaf(-2.f, cc[1], b21);
                    float d10 = fmaf(-2.f, cc[2], b20);
                    float d11 = fmaf(-2.f, cc[3], b21);
                    int s0 = mt * 2, s1 = mt * 2 + 1;
                    if (d00 < runv[s0]) { runv[s0] = d00; runi[s0] = ng0; }
                    if (d01 < runv[s0]) { runv[s0] = d01; runi[s0] = ng1; }
                    if (d10 < runv[s1]) { runv[s1] = d10; runi[s1] = ng0; }
                    if (d11 < runv[s1]) { runv[s1] = d11; runi[s1] = ng1; }
                }
            }
        }
        __syncthreads();
    }

    // cross-lane reduce (lanes sharing a row differ only in tg = lane&3)
    float* minv_s = (float*)(smem + 1024);
    int*   mini_s = (int*)(smem + 3072);
    const int g = lane >> 2;
#pragma unroll
    for (int s = 0; s < 8; s++) {
        float v = runv[s];
        int ix = runi[s];
#pragma unroll
        for (int off = 1; off <= 2; off <<= 1) {
            float ov = __shfl_xor_sync(0xffffffffu, v, off);
            int   oi = __shfl_xor_sync(0xffffffffu, ix, off);
            if (ov < v || (ov == v && oi < ix)) { v = ov; ix = oi; }
        }
        if (tg == 0) {
            int rloc = (s >> 1) * 16 + (s & 1) * 8 + g;
            minv_s[wid * 64 + rloc] = v;
            mini_s[wid * 64 + rloc] = ix;
        }
    }
    __syncthreads();
    if (tid < 128) {
        int row = tid;
        int wmr = row >> 6, rl = row & 63;
        float v = 3.4e38f;
        int ix = 0x7fffffff;
#pragma unroll
        for (int j = 0; j < 4; j++) {
            float ov = minv_s[(wmr * 4 + j) * 64 + rl];
            int   oi = mini_s[(wmr * 4 + j) * 64 + rl];
            if (ov < v || (ov == v && oi < ix)) { v = ov; ix = oi; }
        }
        g_minpart[split * M + row0 + row] = v;
        g_argpart[split * M + row0 + row] = ix;
    }
}

// ---------------- K3: combine splits, patch scores, per-batch argmax ----------------
__global__ void k3_scores(int M, int P)
{
    int b = blockIdx.x;
    int tid = threadIdx.x;
    float bestv = -1.f;
    int bestm = 0x7fffffff, bestnn = 0;
    for (int p = tid; p < P; p += blockDim.x) {
        int m = b * P + p;
        float v = 3.4e38f;
        int ix = 0x7fffffff;
#pragma unroll
        for (int s = 0; s < NSPL; s++) {
            float pv = g_minpart[s * M + m];
            int   pi = g_argpart[s * M + m];
            if (pv < v || (pv == v && pi < ix)) { v = pv; ix = pi; }
        }
        float sc = sqrtf(fmaxf(g_a2[m] + v, 0.f));
        if (sc > bestv || (sc == bestv && m < bestm)) { bestv = sc; bestm = m; bestnn = ix; }
    }
    __shared__ float sv[256];
    __shared__ int sm_[256];
    __shared__ int sn[256];
    sv[tid] = bestv; sm_[tid] = bestm; sn[tid] = bestnn;
    __syncthreads();
    for (int off = 128; off; off >>= 1) {
        if (tid < off) {
            if (sv[tid + off] > sv[tid] ||
                (sv[tid + off] == sv[tid] && sm_[tid + off] < sm_[tid])) {
                sv[tid] = sv[tid + off]; sm_[tid] = sm_[tid + off]; sn[tid] = sn[tid + off];
            }
        }
        __syncthreads();
    }
    if (tid == 0) { g_score[b] = sv[0]; g_mp[b] = sm_[0]; g_nn[b] = sn[0]; }
}

// ---------------- K4: per (batch, split-of-32) local 9-NN ----------------
__global__ void k4_knn(const float* __restrict__ C, int N)
{
    int sp = blockIdx.x;   // 0..31
    int b = blockIdx.y;
    int tid = threadIdx.x; // 256
    __shared__ __align__(16) float q[DD];
    __shared__ float dv[K4CH];
    __shared__ float rv[256];
    __shared__ int   rc[256];

    int nn = g_nn[b];
    for (int j = tid; j < DD; j += 256) q[j] = C[(size_t)nn * DD + j];
    __syncthreads();
    float qn = g_b2[nn];
    int n0 = sp * K4CH;
    const float4* pq = (const float4*)q;
    for (int c = tid; c < K4CH; c += 256) {
        int n = n0 + c;
        const float4* p = (const float4*)(C + (size_t)n * DD);
        float dot = 0.f;
#pragma unroll 8
        for (int j = 0; j < DD / 4; j++) {
            float4 a = p[j], bq = pq[j];
            dot += a.x * bq.x + a.y * bq.y + a.z * bq.z + a.w * bq.w;
        }
        dv[c] = fmaxf(qn + g_b2[n] - 2.f * dot, 0.f);
    }
    __syncthreads();

    for (int k = 0; k < 9; k++) {
        float v = 3.4e38f;
        int ci = 0x7fffffff;
        for (int c = tid; c < K4CH; c += 256) {
            float cv = dv[c];
            if (cv < v || (cv == v && c < ci)) { v = cv; ci = c; }
        }
        rv[tid] = v; rc[tid] = ci;
        __syncthreads();
        for (int off = 128; off; off >>= 1) {
            if (tid < off) {
                if (rv[tid + off] < rv[tid] ||
                    (rv[tid + off] == rv[tid] && rc[tid + off] < rc[tid])) {
                    rv[tid] = rv[tid + off]; rc[tid] = rc[tid + off];
                }
            }
            __syncthreads();
        }
        if (tid == 0) {
            int o = (b * K4SPL + sp) * 9 + k;
            g_knn_v[o] = rv[0];
            g_knn_i[o] = n0 + rc[0];
            dv[rc[0]] = 3.4e38f;
        }
        __syncthreads();
    }
}

// ---------------- K5: merge candidates, d_sup, softmax weight ----------------
__global__ void k5_final(const float* __restrict__ A, const float* __restrict__ C,
                         float* __restrict__ out)
{
    int b = blockIdx.x;
    int lane = threadIdx.x; // 32
    float lv[9];
    int ln[9];
#pragma unroll
    for (int t = 0; t < 9; t++) {
        int i = lane + 32 * t;
        lv[t] = g_knn_v[b * NCAND + i];
        ln[t] = g_knn_i[b * NCAND + i];
    }
    int sup[9];
    for (int k = 0; k < 9; k++) {
        float v = 3.4e38f;
        int nix = 0x7fffffff;
#pragma unroll
        for (int t = 0; t < 9; t++)
            if (lv[t] < v || (lv[t] == v && ln[t] < nix)) { v = lv[t]; nix = ln[t]; }
#pragma unroll
        for (int off = 16; off; off >>= 1) {
            float ov = __shfl_xor_sync(0xffffffffu, v, off);
            int   oi = __shfl_xor_sync(0xffffffffu, nix, off);
            if (ov < v || (ov == v && oi < nix)) { v = ov; nix = oi; }
        }
        sup[k] = nix;
#pragma unroll
        for (int t = 0; t < 9; t++)
            if (ln[t] == nix) lv[t] = 3.4e38f;
    }

    int mp = g_mp[b];
    float a2m = g_a2[mp];
    const float4* fq = (const float4*)(A + (size_t)mp * DD);
    float dsup[9];
    for (int k = 0; k < 9; k++) {
        const float4* fc = (const float4*)(C + (size_t)sup[k] * DD);
        float dot = 0.f;
        for (int j = lane; j < DD / 4; j += 32) {
            float4 x = fq[j], y = fc[j];
            dot += x.x * y.x + x.y * y.y + x.z * y.z + x.w * y.w;
        }
#pragma unroll
        for (int off = 16; off; off >>= 1) dot += __shfl_xor_sync(0xffffffffu, dot, off);
        dsup[k] = sqrtf(fmaxf(a2m + g_b2[sup[k]] - 2.f * dot, 0.f));
    }
    float mx = dsup[0];
#pragma unroll
    for (int k = 1; k < 9; k++) mx = fmaxf(mx, dsup[k]);
    float s = 0.f;
#pragma unroll
    for (int k = 0; k < 9; k++) s += expf(dsup[k] - mx);
    float w = 1.f - expf(dsup[0] - mx) / s;
    if (lane == 0) out[b] = w * g_score[b];
}

// ---------------- launch ----------------
extern "C" void kernel_launch(void* const* d_in, const int* in_sizes, int n_in,
                              void* d_out, int out_size)
{
    const float* A = (const float*)d_in[0];  // embedding [M, 384]
    const float* C = (const float*)d_in[1];  // coreset   [N, 384]
    float* out = (float*)d_out;

    int M = in_sizes[0] / DD;   // 6272
    int N = in_sizes[1] / DD;   // 16384
    int B = out_size;           // 8
    int P = M / B;              // 784

    {   // K0: staging (chunk-planar, hi|lo, pre-swizzled)
        int tot = (M + N) * 96;
        int blocks = (tot + 255) / 256;
        k0_stage<<<blocks, 256>>>(A, C, M, N);
    }
    {   // K1: norms
        int warps = M + N;
        int blocks = (warps * 32 + 255) / 256;
        k1_norms<<<blocks, 256>>>(A, C, M, N);
    }
    {   // K2: bulk-DMA + ldmatrix + mma distance-min GEMM
        cudaFuncSetAttribute(k2_mm, cudaFuncAttributeMaxDynamicSharedMemorySize, SMEM_TOTAL);
        dim3 grid(M / MT, NSPL);
        k2_mm<<<grid, 256, SMEM_TOTAL>>>(M);
    }
    k3_scores<<<B, 256>>>(M, P);
    {
        dim3 grid(K4SPL, B);
        k4_knn<<<grid, 256>>>(C, N);
    }
    k5_final<<<B, 32>>>(A, C, out);
}